// round 1
// baseline (speedup 1.0000x reference)
#include <cuda_runtime.h>
#include <cuda_bf16.h>

// Erosion (min filter) k=18, SAME padding (pad_lo=8, pad_hi=9), on y = x*0.5+0.5.
// Input/output: NCHW (32,3,512,512) fp32 -> 96 planes of 512x512.
// Fused separable min filter: horizontal pass into smem, vertical pass to gmem.
// van Herk/Gil-Werman: per 16-output chunk, 33 reads (suffix sweep + prefix sweep).

#define W 512
#define H 512
#define TX 128            // output tile cols
#define TY 64             // output tile rows
#define KW 18
#define PADLO 8
#define HX (TX + KW - 1)  // 145 input cols per tile
#define HY (TY + KW - 1)  // 81 input rows per tile
#define SH_STRIDE 129     // padded stride for horizontal-result buffer (bank-conflict-free)
#define NTHREADS 512

#define SMEM_FLOATS (HY * HX + HY * SH_STRIDE)
#define SMEM_BYTES (SMEM_FLOATS * 4)

__global__ __launch_bounds__(NTHREADS, 2)
void erode18_kernel(const float* __restrict__ x, float* __restrict__ out) {
    extern __shared__ float sm[];
    float* s_in = sm;                 // HY x HX   (raw input tile, transformed)
    float* s_h  = sm + HY * HX;       // HY x SH_STRIDE (horizontal min results, TX valid cols)

    const int tid = threadIdx.x;
    const int colBase = blockIdx.x * TX;
    const int rowBase = blockIdx.y * TY;
    const long plane = (long)blockIdx.z * (W * H);
    const float INF = __int_as_float(0x7f800000);

    // ---- Phase 1: cooperative load with transform, +inf out of bounds ----
    #pragma unroll 4
    for (int idx = tid; idx < HY * HX; idx += NTHREADS) {
        int r = idx / HX;
        int c = idx - r * HX;
        int gr = rowBase - PADLO + r;
        int gc = colBase - PADLO + c;
        float v = INF;
        if ((unsigned)gr < (unsigned)H && (unsigned)gc < (unsigned)W)
            v = fmaf(x[plane + gr * W + gc], 0.5f, 0.5f);
        s_in[idx] = v;
    }
    __syncthreads();

    // ---- Phase 2: horizontal min-18 for every input row (HY rows) ----
    // Items: (TX/16)=8 chunks x HY rows = 648. Chunk computes 16 outputs from
    // 33 sequential values via suffix(18)+prefix(15) sweeps.
    for (int j = tid; j < HY * (TX / 16); j += NTHREADS) {
        int chunk = j / HY;            // consecutive lanes -> consecutive rows
        int rr = j - chunk * HY;
        int c0 = chunk * 16;
        const float* row = s_in + rr * HX + c0;

        float S[16];
        float s = row[17];
        #pragma unroll
        for (int i = 16; i >= 0; --i) {
            s = fminf(s, row[i]);
            if (i <= 15) S[i] = s;      // S[i] = min(row[i..17])
        }
        float ov[16];
        ov[0] = S[0];
        float p = row[18];
        ov[1] = fminf(S[1], p);
        #pragma unroll
        for (int i = 2; i <= 15; ++i) {
            p = fminf(p, row[i + 17]);  // p = min(row[18..i+17])
            ov[i] = fminf(S[i], p);
        }
        float* hrow = s_h + rr * SH_STRIDE + c0;
        #pragma unroll
        for (int i = 0; i < 16; ++i) hrow[i] = ov[i];
    }
    __syncthreads();

    // ---- Phase 3: vertical min-18, thread-per-column, coalesced gmem stores ----
    // 128 cols x 4 row-chunks(16) = 512 items = one per thread.
    {
        int c = tid & (TX - 1);
        int o0 = (tid >> 7) * 16;
        const float* colp = s_h + c;

        float S[16];
        float s = colp[(o0 + 17) * SH_STRIDE];
        #pragma unroll
        for (int i = 16; i >= 0; --i) {
            s = fminf(s, colp[(o0 + i) * SH_STRIDE]);
            if (i <= 15) S[i] = s;
        }
        float ov[16];
        ov[0] = S[0];
        float p = colp[(o0 + 18) * SH_STRIDE];
        ov[1] = fminf(S[1], p);
        #pragma unroll
        for (int i = 2; i <= 15; ++i) {
            p = fminf(p, colp[(o0 + i + 17) * SH_STRIDE]);
            ov[i] = fminf(S[i], p);
        }
        float* op = out + plane + (long)(rowBase + o0) * W + colBase + c;
        #pragma unroll
        for (int i = 0; i < 16; ++i) op[(long)i * W] = ov[i];
    }
}

extern "C" void kernel_launch(void* const* d_in, const int* in_sizes, int n_in,
                              void* d_out, int out_size) {
    const float* x = (const float*)d_in[0];
    float* out = (float*)d_out;

    // Idempotent, host-side, not captured into the graph; safe to call per launch.
    cudaFuncSetAttribute(erode18_kernel,
                         cudaFuncAttributeMaxDynamicSharedMemorySize, SMEM_BYTES);

    dim3 grid(W / TX, H / TY, 96);   // 4 x 8 x 96 = 3072 blocks
    erode18_kernel<<<grid, NTHREADS, SMEM_BYTES>>>(x, out);
}

// round 2
// speedup vs baseline: 1.4234x; 1.4234x over previous
#include <cuda_runtime.h>
#include <cuda_bf16.h>

// Erosion (min filter) k=18, SAME (pad_lo=8, pad_hi=9), on y = x*0.5+0.5.
// NCHW (32,3,512,512) fp32 = 96 planes of 512x512.
//
// 2-phase fused separable min filter, van Herk/Gil-Werman (chunk=16):
//   Phase V: thread-per-column, 33 coalesced gmem row loads, vertical min-18
//            computed in registers, 16 result rows -> smem.
//   Phase H: thread-per-(row,chunk), 33 conflict-free smem reads (stride 529,
//            odd mod 32 => lane->bank bijection), 16 outputs via float4 stores.

#define W 512
#define H 512
#define TY 16
#define PADLO 8
#define S_STRIDE 529          // 8 front pad + 512 + 9 back pad; ODD => conflict-free LDS
#define NTHREADS 512
#define NPAD (8 + 9)          // pad columns per row

__global__ __launch_bounds__(NTHREADS, 3)
void erode18_kernel(const float* __restrict__ x, float* __restrict__ out) {
    __shared__ float s_v[TY * S_STRIDE];   // 33,856 B

    const int tid = threadIdx.x;
    const int rowBase = blockIdx.x * TY;           // 32 row tiles
    const long plane = (long)blockIdx.y * (W * H); // 96 planes
    const float INF = __int_as_float(0x7f800000);

    // ---- Pad columns (logical cols [-8,-1] and [512,520]) = +inf ----
    if (tid < TY * NPAD) {
        int r = tid / NPAD;
        int j = tid - r * NPAD;
        int idx = (j < PADLO) ? j : (512 + j - PADLO) + PADLO; // j<8: 0..7 ; else 520..528
        s_v[r * S_STRIDE + idx] = INF;
    }

    // ---- Phase V: vertical min-18 in registers (van Herk, chunk = 16) ----
    {
        const int c = tid;                 // column 0..511
        const int gr0 = rowBase - PADLO;   // first input row of window
        const float* colp = x + plane + c;

        float S[16];
        float s = INF;
        #pragma unroll
        for (int r = 17; r >= 0; --r) {    // suffix sweep: S[o] = min(rows o..17)
            int gr = gr0 + r;
            float v = INF;
            if ((unsigned)gr < (unsigned)H)
                v = fmaf(colp[(long)gr * W], 0.5f, 0.5f);
            s = fminf(s, v);
            if (r <= 15) S[r] = s;
        }
        s_v[0 * S_STRIDE + PADLO + c] = S[0];
        float p = INF;                     // prefix sweep: rows 18..o+17
        #pragma unroll
        for (int o = 1; o <= 15; ++o) {
            int gr = gr0 + o + 17;
            float v = INF;
            if ((unsigned)gr < (unsigned)H)
                v = fmaf(colp[(long)gr * W], 0.5f, 0.5f);
            p = fminf(p, v);
            s_v[o * S_STRIDE + PADLO + c] = fminf(S[o], p);
        }
    }
    __syncthreads();

    // ---- Phase H: horizontal min-18 from smem, float4 stores ----
    {
        const int r  = tid & (TY - 1);       // 0..15
        const int c0 = (tid >> 4) << 4;      // chunk * 16, 0..496
        // window for outputs c0..c0+15 spans logical cols c0-8..c0+24
        // = smem idx (r*S_STRIDE + c0) + 0..32
        const float* rp = s_v + r * S_STRIDE + c0;

        float S[16];
        float s = INF;
        #pragma unroll
        for (int i = 17; i >= 0; --i) {
            s = fminf(s, rp[i]);
            if (i <= 15) S[i] = s;
        }
        float ov[16];
        ov[0] = S[0];
        float p = INF;
        #pragma unroll
        for (int o = 1; o <= 15; ++o) {
            p = fminf(p, rp[o + 17]);
            ov[o] = fminf(S[o], p);
        }
        float4* o4 = (float4*)(out + plane + (long)(rowBase + r) * W + c0);
        o4[0] = make_float4(ov[0],  ov[1],  ov[2],  ov[3]);
        o4[1] = make_float4(ov[4],  ov[5],  ov[6],  ov[7]);
        o4[2] = make_float4(ov[8],  ov[9],  ov[10], ov[11]);
        o4[3] = make_float4(ov[12], ov[13], ov[14], ov[15]);
    }
}

extern "C" void kernel_launch(void* const* d_in, const int* in_sizes, int n_in,
                              void* d_out, int out_size) {
    const float* x = (const float*)d_in[0];
    float* out = (float*)d_out;
    dim3 grid(H / TY, 96);   // 32 x 96 = 3072 blocks
    erode18_kernel<<<grid, NTHREADS>>>(x, out);
}